// round 14
// baseline (speedup 1.0000x reference)
#include <cuda_runtime.h>
#include <cuda_fp16.h>
#include <cstdint>

// Problem constants
#define S_LEN 1024
#define BATCH 2
#define DM    768
#define NH    12
#define HD    64
#define NTILE 16
#define MROWS (BATCH * S_LEN)   // 2048
#define BK    16
#define NCHUNK (DM / BK)        // 48

// Scratch (device globals — no allocation allowed)
__device__ float  g_q[MROWS * DM];          // Q fp32
__device__ __half g_kh[MROWS * DM];         // K fp16 (GEMM epilogue)
__device__ __half g_vh[MROWS * DM];         // V fp16 (GEMM epilogue)
__device__ float  g_part[BATCH * NTILE * DM];

// ---------------- PTX helpers ----------------
__device__ __forceinline__ uint32_t smem_u32(const void* p) {
    uint32_t a;
    asm("{ .reg .u64 t; cvta.to.shared.u64 t, %1; cvt.u32.u64 %0, t; }"
        : "=r"(a) : "l"(p));
    return a;
}
__device__ __forceinline__ void ldsm_x4(uint32_t& r0, uint32_t& r1,
                                        uint32_t& r2, uint32_t& r3, uint32_t addr) {
    asm volatile("ldmatrix.sync.aligned.m8n8.x4.shared.b16 {%0,%1,%2,%3}, [%4];"
                 : "=r"(r0), "=r"(r1), "=r"(r2), "=r"(r3) : "r"(addr));
}
__device__ __forceinline__ void ldsm_x4_t(uint32_t& r0, uint32_t& r1,
                                          uint32_t& r2, uint32_t& r3, uint32_t addr) {
    asm volatile("ldmatrix.sync.aligned.m8n8.x4.trans.shared.b16 {%0,%1,%2,%3}, [%4];"
                 : "=r"(r0), "=r"(r1), "=r"(r2), "=r"(r3) : "r"(addr));
}
__device__ __forceinline__ void mma16816(float* c, uint32_t a0, uint32_t a1,
                                         uint32_t a2, uint32_t a3,
                                         uint32_t b0, uint32_t b1) {
    asm volatile("mma.sync.aligned.m16n8k16.row.col.f32.f16.f16.f32 "
                 "{%0,%1,%2,%3}, {%4,%5,%6,%7}, {%8,%9}, {%0,%1,%2,%3};"
                 : "+f"(c[0]), "+f"(c[1]), "+f"(c[2]), "+f"(c[3])
                 : "r"(a0), "r"(a1), "r"(a2), "r"(a3), "r"(b0), "r"(b1));
}
__device__ __forceinline__ uint4 cvt8(float4 a, float4 b) {
    __half2 h0 = __floats2half2_rn(a.x, a.y);
    __half2 h1 = __floats2half2_rn(a.z, a.w);
    __half2 h2 = __floats2half2_rn(b.x, b.y);
    __half2 h3 = __floats2half2_rn(b.z, b.w);
    uint4 u;
    u.x = *(uint32_t*)&h0; u.y = *(uint32_t*)&h1;
    u.z = *(uint32_t*)&h2; u.w = *(uint32_t*)&h3;
    return u;
}

// ---------------------------------------------------------------------------
// Fused fp16 HMMA GEMM: stages A from fp32 x and B from fp32 W (native [k][n]
// layout, ldmatrix.trans fragments) with in-register conversion. No prep
// kernels. CTA 128x128, BK=16, 8 warps (2x4), warp tile 64x32.
// z=0 -> g_q fp32; z=1/2 -> g_kh/g_vh fp16.
// ---------------------------------------------------------------------------
#define LDA 24    // A smem stride (halves), conflict-free ldmatrix rows
#define LDB 136   // B smem stride (halves), conflict-free trans rows

__global__ __launch_bounds__(256, 2) void tc_gemm(
    const float* __restrict__ x,
    const float* __restrict__ Wq, const float* __restrict__ Wk,
    const float* __restrict__ Wv,
    const float* __restrict__ bq, const float* __restrict__ bk,
    const float* __restrict__ bv)
{
    __shared__ __half As[2][128 * LDA];   // [m][k] 128x16
    __shared__ __half Bs[2][BK * LDB];    // [k][n] 16x128

    const int tid  = threadIdx.x;
    const int warp = tid >> 5;
    const int lane = tid & 31;
    const int wm = warp >> 2;
    const int wn = warp & 3;

    const int z  = blockIdx.z;
    const int n0 = blockIdx.x * 128;
    const int m0 = blockIdx.y * 128;
    const float* bias = (z == 0) ? bq : (z == 1) ? bk : bv;
    const float* W    = (z == 0) ? Wq : (z == 1) ? Wk : Wv;

    // Loader mapping (fp32 sources)
    const int aRow = tid >> 1;            // 0..127
    const int aCol = (tid & 1) * 8;       // 0 or 8
    const int bRow = tid >> 4;            // 0..15
    const int bSeg = (tid & 15) * 8;      // 0..120

    const float* Aptr = x + (size_t)(m0 + aRow) * DM + aCol;
    const float* Wptr = W + (size_t)bRow * DM + n0 + bSeg;

    // ldmatrix lane addressing
    const int a_r = lane & 15, a_c = (lane >> 4) * 8;
    const int b_k = lane & 15, b_n8 = (lane >> 4) * 8;

    const uint32_t asm_base = smem_u32(&As[0][0]);
    const uint32_t bsm_base = smem_u32(&Bs[0][0]);
    const uint32_t bufA = 128 * LDA * 2;
    const uint32_t bufB = BK * LDB * 2;

    float acc[4][4][4];
    #pragma unroll
    for (int i = 0; i < 4; i++)
        #pragma unroll
        for (int j = 0; j < 4; j++)
            #pragma unroll
            for (int r = 0; r < 4; r++) acc[i][j][r] = 0.0f;

    // Prologue: chunk 0 -> buffer 0 (load fp32, cvt, store fp16)
    {
        float4 a0 = *(const float4*)(Aptr + 0);
        float4 a1 = *(const float4*)(Aptr + 4);
        float4 b0 = *(const float4*)(Wptr + 0);
        float4 b1 = *(const float4*)(Wptr + 4);
        *(uint4*)&As[0][aRow * LDA + aCol] = cvt8(a0, a1);
        *(uint4*)&Bs[0][bRow * LDB + bSeg] = cvt8(b0, b1);
    }
    __syncthreads();

    int buf = 0;
    for (int c = 0; c < NCHUNK; c++) {
        const bool has_next = (c + 1) < NCHUNK;
        float4 pA0, pA1, pB0, pB1;
        if (has_next) {
            const float* An = Aptr + (c + 1) * BK;
            const float* Wn = Wptr + (size_t)(c + 1) * BK * DM;
            pA0 = *(const float4*)(An + 0);
            pA1 = *(const float4*)(An + 4);
            pB0 = *(const float4*)(Wn + 0);
            pB1 = *(const float4*)(Wn + 4);
        }

        const uint32_t ab = asm_base + buf * bufA;
        const uint32_t bb = bsm_base + buf * bufB;

        uint32_t a[4][4];
        #pragma unroll
        for (int mt = 0; mt < 4; mt++) {
            uint32_t addr = ab + ((wm * 64 + mt * 16 + a_r) * LDA + a_c) * 2;
            ldsm_x4(a[mt][0], a[mt][1], a[mt][2], a[mt][3], addr);
        }
        uint32_t b[2][4];
        #pragma unroll
        for (int np = 0; np < 2; np++) {
            uint32_t addr = bb + (b_k * LDB + wn * 32 + np * 16 + b_n8) * 2;
            ldsm_x4_t(b[np][0], b[np][1], b[np][2], b[np][3], addr);
        }
        #pragma unroll
        for (int mt = 0; mt < 4; mt++)
            #pragma unroll
            for (int nt = 0; nt < 4; nt++)
                mma16816(acc[mt][nt],
                         a[mt][0], a[mt][1], a[mt][2], a[mt][3],
                         b[nt >> 1][(nt & 1) * 2], b[nt >> 1][(nt & 1) * 2 + 1]);

        if (has_next) {
            const int nb = buf ^ 1;
            *(uint4*)&As[nb][aRow * LDA + aCol] = cvt8(pA0, pA1);
            *(uint4*)&Bs[nb][bRow * LDB + bSeg] = cvt8(pB0, pB1);
            __syncthreads();
            buf = nb;
        }
    }

    const int g  = lane >> 2;
    const int tg = lane & 3;
    if (z == 0) {
        #pragma unroll
        for (int mt = 0; mt < 4; mt++) {
            const int row = m0 + wm * 64 + mt * 16 + g;
            float* Crow0 = g_q + (size_t)row * DM;
            float* Crow1 = g_q + (size_t)(row + 8) * DM;
            #pragma unroll
            for (int nt = 0; nt < 4; nt++) {
                const int col = n0 + wn * 32 + nt * 8 + tg * 2;
                const float bx = __ldg(&bias[col]);
                const float by = __ldg(&bias[col + 1]);
                *(float2*)&Crow0[col] = make_float2(acc[mt][nt][0] + bx, acc[mt][nt][1] + by);
                *(float2*)&Crow1[col] = make_float2(acc[mt][nt][2] + bx, acc[mt][nt][3] + by);
            }
        }
    } else {
        __half* Ch = (z == 1) ? g_kh : g_vh;
        #pragma unroll
        for (int mt = 0; mt < 4; mt++) {
            const int row = m0 + wm * 64 + mt * 16 + g;
            __half* Crow0 = Ch + (size_t)row * DM;
            __half* Crow1 = Ch + (size_t)(row + 8) * DM;
            #pragma unroll
            for (int nt = 0; nt < 4; nt++) {
                const int col = n0 + wn * 32 + nt * 8 + tg * 2;
                const float bx = __ldg(&bias[col]);
                const float by = __ldg(&bias[col + 1]);
                __half2 h0 = __floats2half2_rn(acc[mt][nt][0] + bx, acc[mt][nt][1] + by);
                __half2 h1 = __floats2half2_rn(acc[mt][nt][2] + bx, acc[mt][nt][3] + by);
                *(uint32_t*)&Crow0[col] = *(uint32_t*)&h0;
                *(uint32_t*)&Crow1[col] = *(uint32_t*)&h1;
            }
        }
    }
}

// ---------------------------------------------------------------------------
// Windowed attention, v6 (unchanged from R13)
// ---------------------------------------------------------------------------
#define KVS 72   // k/v smem row stride in halves

__global__ __launch_bounds__(256, 3) void attn_kernel()
{
    const int tile = blockIdx.x;
    const int h    = blockIdx.y;
    const int b    = blockIdx.z;
    const int s0   = tile * 64;
    const int colbase = h * HD;

    extern __shared__ __align__(16) char smraw[];
    float*  q_sm = (float*)smraw;                       // 64 x 68 f32 (then weights)
    __half* k_sm = (__half*)(smraw + 17408);            // 128 x 72 f16
    __half* v_sm = (__half*)(smraw + 17408 + 18432);    // 128 x 72 f16
    float*  p_sm = (float*)(smraw + 17408);             // reuse k region for pool

    const int tid = threadIdx.x;

    for (int i = tid; i < 64 * 16; i += 256) {
        int row = i >> 4;
        int c4  = (i & 15) << 2;
        float4 v = *(const float4*)&g_q[((b * S_LEN) + s0 + row) * DM + colbase + c4];
        *(float4*)&q_sm[row * 68 + c4] = v;
    }
    for (int i = tid; i < 128 * 8; i += 256) {
        int row  = i >> 3;
        int c8   = (i & 7) << 3;
        int srow = s0 - 32 + row;
        uint4 ku = make_uint4(0u, 0u, 0u, 0u);
        uint4 vu = make_uint4(0u, 0u, 0u, 0u);
        if (srow >= 0 && srow < S_LEN) {
            size_t off = ((size_t)(b * S_LEN) + srow) * DM + colbase + c8;
            ku = *(const uint4*)&g_kh[off];
            vu = *(const uint4*)&g_vh[off];
        }
        *(uint4*)&k_sm[row * KVS + c8] = ku;
        *(uint4*)&v_sm[row * KVS + c8] = vu;
    }
    __syncthreads();

    const int grp = tid >> 4;
    const int sub = tid & 15;
    const int qA  = grp * 4;

    int ro[5];
    #pragma unroll
    for (int j = 0; j < 5; j++) {
        int rsm = qA + sub + 16 * j;
        if (rsm > 127) rsm = 127;
        ro[j] = rsm * KVS;
    }

    float sc[5][4];
    #pragma unroll
    for (int j = 0; j < 5; j++)
        #pragma unroll
        for (int c = 0; c < 4; c++) sc[j][c] = 0.f;

    #pragma unroll
    for (int dc = 0; dc < 16; dc++) {
        float4 qv[4];
        #pragma unroll
        for (int c = 0; c < 4; c++)
            qv[c] = *(const float4*)&q_sm[(qA + c) * 68 + dc * 4];
        #pragma unroll
        for (int j = 0; j < 5; j++) {
            uint2 kraw = *(const uint2*)&k_sm[ro[j] + dc * 4];
            float2 k01 = __half22float2(*(__half2*)&kraw.x);
            float2 k23 = __half22float2(*(__half2*)&kraw.y);
            #pragma unroll
            for (int c = 0; c < 4; c++) {
                sc[j][c] = fmaf(qv[c].x, k01.x, sc[j][c]);
                sc[j][c] = fmaf(qv[c].y, k01.y, sc[j][c]);
                sc[j][c] = fmaf(qv[c].z, k23.x, sc[j][c]);
                sc[j][c] = fmaf(qv[c].w, k23.y, sc[j][c]);
            }
        }
    }

    #pragma unroll
    for (int j = 0; j < 5; j++) {
        int rsm = qA + sub + 16 * j;
        int gk  = s0 + rsm - 32;
        bool rowok = (rsm <= 127) && (gk >= 0) && (gk < S_LEN);
        #pragma unroll
        for (int c = 0; c < 4; c++) {
            int w = sub + 16 * j - c;
            bool ok = rowok && (w >= 0) && (w <= 64);
            sc[j][c] = ok ? sc[j][c] * 0.125f : -1e9f;
        }
    }

    float mx[4], lsum[4];
    #pragma unroll
    for (int c = 0; c < 4; c++) {
        float m = -1e30f;
        #pragma unroll
        for (int j = 0; j < 5; j++) m = fmaxf(m, sc[j][c]);
        #pragma unroll
        for (int o = 1; o <= 8; o <<= 1)
            m = fmaxf(m, __shfl_xor_sync(0xffffffffu, m, o, 16));
        mx[c] = m;
    }
    #pragma unroll
    for (int c = 0; c < 4; c++) {
        float l = 0.f;
        #pragma unroll
        for (int j = 0; j < 5; j++) { sc[j][c] = __expf(sc[j][c] - mx[c]); l += sc[j][c]; }
        #pragma unroll
        for (int o = 1; o <= 8; o <<= 1)
            l += __shfl_xor_sync(0xffffffffu, l, o, 16);
        lsum[c] = 1.0f / l;
    }

    #pragma unroll
    for (int j = 0; j < 5; j++) {
        int slot = sub + 16 * j;
        if (slot < 68) {
            #pragma unroll
            for (int c = 0; c < 4; c++)
                q_sm[(qA + c) * 68 + slot] = sc[j][c] * lsum[c];
        }
    }
    __syncwarp();

    const int d0 = sub * 4;
    float4 acc[4];
    #pragma unroll
    for (int c = 0; c < 4; c++) acc[c] = make_float4(0.f, 0.f, 0.f, 0.f);

    #pragma unroll
    for (int tb = 0; tb < 17; tb++) {
        float4 wv[4];
        #pragma unroll
        for (int c = 0; c < 4; c++)
            wv[c] = *(const float4*)&q_sm[(qA + c) * 68 + tb * 4];
        #pragma unroll
        for (int s = 0; s < 4; s++) {
            int t = tb * 4 + s;
            uint2 vraw = *(const uint2*)&v_sm[(qA + t) * KVS + d0];
            float2 v01 = __half22float2(*(__half2*)&vraw.x);
            float2 v23 = __half22float2(*(__half2*)&vraw.y);
            float w0 = (s == 0) ? wv[0].x : (s == 1) ? wv[0].y : (s == 2) ? wv[0].z : wv[0].w;
            float w1 = (s == 0) ? wv[1].x : (s == 1) ? wv[1].y : (s == 2) ? wv[1].z : wv[1].w;
            float w2 = (s == 0) ? wv[2].x : (s == 1) ? wv[2].y : (s == 2) ? wv[2].z : wv[2].w;
            float w3 = (s == 0) ? wv[3].x : (s == 1) ? wv[3].y : (s == 2) ? wv[3].z : wv[3].w;
            acc[0].x = fmaf(w0, v01.x, acc[0].x); acc[0].y = fmaf(w0, v01.y, acc[0].y);
            acc[0].z = fmaf(w0, v23.x, acc[0].z); acc[0].w = fmaf(w0, v23.y, acc[0].w);
            acc[1].x = fmaf(w1, v01.x, acc[1].x); acc[1].y = fmaf(w1, v01.y, acc[1].y);
            acc[1].z = fmaf(w1, v23.x, acc[1].z); acc[1].w = fmaf(w1, v23.y, acc[1].w);
            acc[2].x = fmaf(w2, v01.x, acc[2].x); acc[2].y = fmaf(w2, v01.y, acc[2].y);
            acc[2].z = fmaf(w2, v23.x, acc[2].z); acc[2].w = fmaf(w2, v23.y, acc[2].w);
            acc[3].x = fmaf(w3, v01.x, acc[3].x); acc[3].y = fmaf(w3, v01.y, acc[3].y);
            acc[3].z = fmaf(w3, v23.x, acc[3].z); acc[3].w = fmaf(w3, v23.y, acc[3].w);
        }
    }

    float4 ps;
    ps.x = acc[0].x + acc[1].x + acc[2].x + acc[3].x;
    ps.y = acc[0].y + acc[1].y + acc[2].y + acc[3].y;
    ps.z = acc[0].z + acc[1].z + acc[2].z + acc[3].z;
    ps.w = acc[0].w + acc[1].w + acc[2].w + acc[3].w;

    __syncthreads();
    *(float4*)&p_sm[grp * 64 + d0] = ps;
    __syncthreads();

    if (tid < 64) {
        float tot = 0.f;
        #pragma unroll
        for (int gpart = 0; gpart < 16; gpart++)
            tot += p_sm[gpart * 64 + tid];
        g_part[((b * NTILE) + tile) * DM + h * HD + tid] = tot;
    }
}

// ---------------------------------------------------------------------------
__global__ __launch_bounds__(256) void fc_kernel(
    const float* __restrict__ Wfc, const float* __restrict__ bfc,
    float* __restrict__ out)
{
    __shared__ float pooled[DM];
    __shared__ float red[4][64];
    const int b   = blockIdx.y;
    const int tid = threadIdx.x;

    for (int i = tid; i < DM; i += 256) {
        float s = 0.f;
        #pragma unroll
        for (int t = 0; t < NTILE; t++)
            s += g_part[(b * NTILE + t) * DM + i];
        pooled[i] = s * (1.0f / (float)S_LEN);
    }
    __syncthreads();

    const int split = tid >> 6;
    const int olocal = tid & 63;
    const int o = blockIdx.x * 64 + olocal;
    float acc = 0.f;
    const int i0 = split * 192;
    #pragma unroll 4
    for (int i = i0; i < i0 + 192; i++)
        acc = fmaf(pooled[i], Wfc[i * DM + o], acc);
    red[split][olocal] = acc;
    __syncthreads();
    if (tid < 64) {
        float r = red[0][tid] + red[1][tid] + red[2][tid] + red[3][tid] + bfc[blockIdx.x * 64 + tid];
        out[b * DM + blockIdx.x * 64 + tid] = fmaxf(r, 0.f);
    }
}

// ---------------------------------------------------------------------------
extern "C" void kernel_launch(void* const* d_in, const int* in_sizes, int n_in,
                              void* d_out, int out_size)
{
    const float* x   = (const float*)d_in[0];
    const float* Wq  = (const float*)d_in[1];
    const float* bq  = (const float*)d_in[2];
    const float* Wk  = (const float*)d_in[3];
    const float* bk  = (const float*)d_in[4];
    const float* Wv  = (const float*)d_in[5];
    const float* bv  = (const float*)d_in[6];
    const float* Wfc = (const float*)d_in[7];
    const float* bfc = (const float*)d_in[8];
    float* out = (float*)d_out;

    // Fused conversion + fp16 HMMA GEMMs (no prep kernels)
    tc_gemm<<<dim3(DM / 128, MROWS / 128, 3), 256>>>(x, Wq, Wk, Wv, bq, bk, bv);

    // attn smem: 17408 (q f32) + 2*18432 (k/v f16 stride 72) = 54272 B
    const int attn_smem = 17408 + 2 * 18432;
    cudaFuncSetAttribute(attn_kernel,
                         cudaFuncAttributeMaxDynamicSharedMemorySize, attn_smem);
    attn_kernel<<<dim3(NTILE, NH, BATCH), 256, attn_smem>>>();

    fc_kernel<<<dim3(DM / 64, BATCH), 256>>>(Wfc, bfc, out);
}